// round 14
// baseline (speedup 1.0000x reference)
#include <cuda_runtime.h>
#include <cuda_fp16.h>
#include <cstdint>

#define N_PIX   6912
#define WIDTH   96
#define CFEAT   16
#define CHUNK   64
#define NCHUNKS 108                 // N_PIX / CHUNK
#define MBLK    54                  // m-blocks of 128 rows (8 warps x 16 rows)
#define NSPLIT  6                   // column splits
#define CPC     (NCHUNKS / NSPLIT)  // 18 chunks per CTA
#define NBLOCKS (MBLK * NSPLIT)     // 324
#define THREADS 256
#define LOG2E   1.4426950408889634f
#define FSTRIDE 136                 // bytes per channel row in f2 chunk (pad: 2-way max conflict)
#define FCHUNK  (16 * FSTRIDE)      // 2176 bytes per chunk
#define FCP16   (FCHUNK / 16)       // 136 16B packets

typedef unsigned long long u64;

__device__ __forceinline__ u64 pk2(float lo, float hi) {
    u64 r; asm("mov.b64 %0, {%1, %2};" : "=l"(r) : "f"(lo), "f"(hi)); return r;
}
__device__ __forceinline__ void unpk2(float& lo, float& hi, u64 v) {
    asm("mov.b64 {%0, %1}, %2;" : "=f"(lo), "=f"(hi) : "l"(v));
}
__device__ __forceinline__ u64 fma2(u64 a, u64 b, u64 c) {
    u64 r; asm("fma.rn.f32x2 %0, %1, %2, %3;" : "=l"(r) : "l"(a), "l"(b), "l"(c)); return r;
}
__device__ __forceinline__ u64 add2(u64 a, u64 b) {
    u64 r; asm("add.rn.f32x2 %0, %1, %2;" : "=l"(r) : "l"(a), "l"(b)); return r;
}
__device__ __forceinline__ float ex2f(float a) {
    float r; asm("ex2.approx.ftz.f32 %0, %1;" : "=f"(r) : "f"(a)); return r;
}
__device__ __forceinline__ uint32_t pkh2(float hi, float lo) {
    uint32_t r; asm("cvt.rn.f16x2.f32 %0, %1, %2;" : "=r"(r) : "f"(hi), "f"(lo)); return r;
}
__device__ __forceinline__ uint32_t sm_u32(const void* p) {
    uint32_t a;
    asm("{ .reg .u64 t; cvta.to.shared.u64 t, %1; cvt.u32.u64 %0, t; }" : "=r"(a) : "l"(p));
    return a;
}
__device__ __forceinline__ void cpasync16(uint32_t sa, const void* g) {
    asm volatile("cp.async.ca.shared.global [%0], [%1], 16;" :: "r"(sa), "l"(g) : "memory");
}
// m16n8k16 row.col f16 inputs, f32 accumulate (sm_80+, legal at compute_103)
__device__ __forceinline__ void mma16816(float* c, uint32_t a0, uint32_t a1,
                                         uint32_t a2, uint32_t a3,
                                         uint32_t b0, uint32_t b1) {
    asm volatile(
        "mma.sync.aligned.m16n8k16.row.col.f32.f16.f16.f32 "
        "{%0,%1,%2,%3}, {%4,%5,%6,%7}, {%8,%9}, {%0,%1,%2,%3};"
        : "+f"(c[0]), "+f"(c[1]), "+f"(c[2]), "+f"(c[3])
        : "r"(a0), "r"(a1), "r"(a2), "r"(a3), "r"(b0), "r"(b1));
}
// b = x.p - h1 - h2 (exp2 domain, packed clean/noisy); returns e1 - e2 in f32
__device__ __forceinline__ float dexp(ulonglong2 g0, ulonglong2 g1,
                                      u64 X, u64 Y, u64 Z, u64 H) {
    u64 aa = fma2(X, g0.x, H);
    aa = fma2(Y, g0.y, aa);
    aa = fma2(Z, g1.x, aa);
    aa = add2(aa, g1.y);
    float p1, p2; unpk2(p1, p2, aa);
    return ex2f(p1) - ex2f(p2);
}

// Scratch globals (no allocation allowed)
__device__ ulonglong2    g_geo[N_PIX * 2];           // per n: {Px,Pnx},{Py,Pny} | {Pz,Pnz},{-h2L,-h2nL}
__device__ unsigned char g_f2n[NCHUNKS * FCHUNK];    // per chunk: [16 chan][64 col] f16, row stride 136B
__device__ float g_part[NBLOCKS];
__device__ float g_fea1[MBLK];
__device__ float g_fea2[NCHUNKS];
__device__ int   g_done = 0;

__global__ __launch_bounds__(64) void precompute_kernel(
    const float* __restrict__ f2, const float* __restrict__ dp2,
    const float* __restrict__ pose, const float* __restrict__ noise)
{
    int tid = threadIdx.x;
    int i = blockIdx.x * 64 + tid;        // block == chunk, tid == column

    float PN[12];
#pragma unroll
    for (int r = 0; r < 3; r++)
#pragma unroll
        for (int c = 0; c < 4; c++) {
            float s = 0.0f;
#pragma unroll
            for (int k = 0; k < 4; k++) s = fmaf(pose[r * 4 + k], noise[k * 4 + c], s);
            PN[r * 4 + c] = s;
        }

    int u = i % WIDTH, v = i / WIDTH;
    float y1 = ((float)u - 48.0f) * (1.0f / 48.0f);
    float y2 = ((float)v - 36.0f) * (1.0f / 48.0f);

    float d2 = dp2[i];
    float q0 = d2, q1 = y1 * d2, q2 = y2 * d2;
    float P[3], Pn[3];
#pragma unroll
    for (int r = 0; r < 3; r++) {
        P[r]  = fmaf(pose[r * 4 + 0], q0, fmaf(pose[r * 4 + 1], q1,
                fmaf(pose[r * 4 + 2], q2, pose[r * 4 + 3])));
        Pn[r] = fmaf(PN[r * 4 + 0], q0, fmaf(PN[r * 4 + 1], q1,
                fmaf(PN[r * 4 + 2], q2, PN[r * 4 + 3])));
    }
    float mh2  = -0.5f * LOG2E * (P[0] * P[0] + P[1] * P[1] + P[2] * P[2]);
    float mh2n = -0.5f * LOG2E * (Pn[0] * Pn[0] + Pn[1] * Pn[1] + Pn[2] * Pn[2]);

    ulonglong2 ga, gb;
    ga.x = pk2(P[0], Pn[0]); ga.y = pk2(P[1], Pn[1]);
    gb.x = pk2(P[2], Pn[2]); gb.y = pk2(mh2, mh2n);
    g_geo[i * 2 + 0] = ga;
    g_geo[i * 2 + 1] = gb;

    float b[CFEAT], s2 = 0.0f;
#pragma unroll
    for (int c = 0; c < CFEAT; c++) { b[c] = f2[c * N_PIX + i]; s2 = fmaf(b[c], b[c], s2); }
    float n2 = sqrtf(s2);
    float sc = 1.0f / (n2 + 1e-8f);

    // f2n fp16 into per-chunk [chan][col] layout (row stride FSTRIDE bytes)
    unsigned char* dst = g_f2n + (size_t)blockIdx.x * FCHUNK;
#pragma unroll
    for (int c = 0; c < CFEAT; c++)
        *(__half*)(dst + c * FSTRIDE + tid * 2) = __float2half_rn(b[c] * sc);

    __shared__ float red[2];
    float r = n2;
#pragma unroll
    for (int s = 16; s > 0; s >>= 1) r += __shfl_down_sync(0xFFFFFFFF, r, s);
    if ((tid & 31) == 0) red[tid >> 5] = r;
    __syncthreads();
    if (tid == 0) g_fea2[blockIdx.x] = red[0] + red[1];
}

struct Smem {
    alignas(16) unsigned char G[2][2048];    // chunk geometry: 64 cols x 32B
    alignas(16) unsigned char F[2][FCHUNK];  // f2n chunk
    float red[8];
    int last;
};

__global__ __launch_bounds__(THREADS) void main_kernel(
    const float* __restrict__ f1, const float* __restrict__ dp1,
    float* __restrict__ out, int out_size)
{
    __shared__ Smem sm;

    int tid = threadIdx.x;
    int lane = tid & 31;
    int wid = tid >> 5;
    int bx = blockIdx.x, by = blockIdx.y;

    // rows owned by this thread (mma A-fragment rows)
    int rowbase = bx * 128 + wid * 16;
    int r0 = rowbase + (lane >> 2);
    int r8 = r0 + 8;

    // packed (clean,noisy) geometry per row, exp2 domain
    u64 X0, Y0, Z0, H0, X8, Y8, Z8, H8;
    {
        int rr[2] = { r0, r8 };
        u64* dst[2][4] = { {&X0, &Y0, &Z0, &H0}, {&X8, &Y8, &Z8, &H8} };
#pragma unroll
        for (int t = 0; t < 2; t++) {
            int m = rr[t];
            int uu = m % WIDTH, vv = m / WIDTH;
            float y1 = ((float)uu - 48.0f) * (1.0f / 48.0f);
            float y2 = ((float)vv - 36.0f) * (1.0f / 48.0f);
            float d = dp1[m];
            float xx = d, xy = y1 * d, xz = y2 * d;
            float h1L = 0.5f * LOG2E * (xx * xx + xy * xy + xz * xz);
            *dst[t][0] = pk2(xx * LOG2E, xx * LOG2E);
            *dst[t][1] = pk2(xy * LOG2E, xy * LOG2E);
            *dst[t][2] = pk2(xz * LOG2E, xz * LOG2E);
            *dst[t][3] = pk2(-h1L, -h1L);
        }
    }

    float accA[4] = {0.f, 0.f, 0.f, 0.f};   // channels 0-7
    float accB[4] = {0.f, 0.f, 0.f, 0.f};   // channels 8-15

    int c0c = by * CPC;
    // prologue: prefetch chunk 0 into buffer 0
    {
        const unsigned char* gs = (const unsigned char*)g_geo + (size_t)c0c * 2048;
        for (int i = tid; i < 128; i += THREADS) cpasync16(sm_u32(sm.G[0] + i * 16), gs + i * 16);
        const unsigned char* fs = g_f2n + (size_t)c0c * FCHUNK;
        for (int i = tid; i < FCP16; i += THREADS) cpasync16(sm_u32(sm.F[0] + i * 16), fs + i * 16);
        asm volatile("cp.async.commit_group;" ::: "memory");
    }

    for (int ci = 0; ci < CPC; ci++) {
        asm volatile("cp.async.wait_group 0;" ::: "memory");
        __syncthreads();

        if (ci + 1 < CPC) {
            int ch = c0c + ci + 1, nb = (ci + 1) & 1;
            const unsigned char* gs = (const unsigned char*)g_geo + (size_t)ch * 2048;
            for (int i = tid; i < 128; i += THREADS) cpasync16(sm_u32(sm.G[nb] + i * 16), gs + i * 16);
            const unsigned char* fs = g_f2n + (size_t)ch * FCHUNK;
            for (int i = tid; i < FCP16; i += THREADS) cpasync16(sm_u32(sm.F[nb] + i * 16), fs + i * 16);
            asm volatile("cp.async.commit_group;" ::: "memory");
        }

        int cur = ci & 1;
        const ulonglong2* Gp = (const ulonglong2*)sm.G[cur];
        const unsigned char* Fb = sm.F[cur];

        // B fragments for this chunk: b[kstep][chanhalf][2]
        uint32_t bfr[4][2][2];
#pragma unroll
        for (int ks = 0; ks < 4; ks++)
#pragma unroll
            for (int h = 0; h < 2; h++) {
                const unsigned char* p = Fb + ((lane >> 2) + h * 8) * FSTRIDE
                                       + (ks * 16 + (lane & 3) * 2) * 2;
                bfr[ks][h][0] = *(const uint32_t*)p;
                bfr[ks][h][1] = *(const uint32_t*)(p + 16);
            }

#pragma unroll
        for (int ks = 0; ks < 4; ks++) {
            int cb = ks * 16 + (lane & 3) * 2;
            ulonglong2 gA0 = Gp[cb * 2 + 0],       gA1 = Gp[cb * 2 + 1];
            ulonglong2 gB0 = Gp[cb * 2 + 2],       gB1 = Gp[cb * 2 + 3];
            ulonglong2 gC0 = Gp[(cb + 8) * 2],     gC1 = Gp[(cb + 8) * 2 + 1];
            ulonglong2 gD0 = Gp[(cb + 9) * 2],     gD1 = Gp[(cb + 9) * 2 + 1];

            float dA0 = dexp(gA0, gA1, X0, Y0, Z0, H0);
            float dA8 = dexp(gA0, gA1, X8, Y8, Z8, H8);
            float dB0 = dexp(gB0, gB1, X0, Y0, Z0, H0);
            float dB8 = dexp(gB0, gB1, X8, Y8, Z8, H8);
            float dC0 = dexp(gC0, gC1, X0, Y0, Z0, H0);
            float dC8 = dexp(gC0, gC1, X8, Y8, Z8, H8);
            float dD0 = dexp(gD0, gD1, X0, Y0, Z0, H0);
            float dD8 = dexp(gD0, gD1, X8, Y8, Z8, H8);

            uint32_t a0 = pkh2(dB0, dA0);   // row r0, cols (cb, cb+1)
            uint32_t a1 = pkh2(dB8, dA8);   // row r8
            uint32_t a2 = pkh2(dD0, dC0);   // row r0, cols (cb+8, cb+9)
            uint32_t a3 = pkh2(dD8, dC8);   // row r8

            mma16816(accA, a0, a1, a2, a3, bfr[ks][0][0], bfr[ks][0][1]);
            mma16816(accB, a0, a1, a2, a3, bfr[ks][1][0], bfr[ks][1][1]);
        }
        __syncthreads();
    }

    // epilogue: dot accumulators with normalized f1 rows
    int ch0 = (lane & 3) * 2, ch1 = ch0 + 1;
    float s0 = 0.f, s8 = 0.f;
#pragma unroll
    for (int c = 0; c < CFEAT; c++) {
        float v0 = f1[c * N_PIX + r0]; s0 = fmaf(v0, v0, s0);
        float v8 = f1[c * N_PIX + r8]; s8 = fmaf(v8, v8, s8);
    }
    float n10 = sqrtf(s0), n18 = sqrtf(s8);
    float inv0 = 1.0f / (n10 + 1e-8f), inv8 = 1.0f / (n18 + 1e-8f);

    float d0 = f1[ch0 * N_PIX + r0] * accA[0] + f1[ch1 * N_PIX + r0] * accA[1]
             + f1[(ch0 + 8) * N_PIX + r0] * accB[0] + f1[(ch1 + 8) * N_PIX + r0] * accB[1];
    float d8 = f1[ch0 * N_PIX + r8] * accA[2] + f1[ch1 * N_PIX + r8] * accA[3]
             + f1[(ch0 + 8) * N_PIX + r8] * accB[2] + f1[(ch1 + 8) * N_PIX + r8] * accB[3];
    float dot = inv0 * d0 + inv8 * d8;

#pragma unroll
    for (int s = 16; s > 0; s >>= 1) dot += __shfl_down_sync(0xFFFFFFFF, dot, s);
    if (lane == 0) sm.red[wid] = dot;
    __syncthreads();
    if (tid == 0) {
        float a = 0.f;
#pragma unroll
        for (int w = 0; w < 8; w++) a += sm.red[w];
        g_part[bx * NSPLIT + by] = a;
    }

    if (by == 0) {
        float fv = ((lane & 3) == 0) ? (n10 + n18) : 0.f;   // each row counted once
#pragma unroll
        for (int s = 16; s > 0; s >>= 1) fv += __shfl_down_sync(0xFFFFFFFF, fv, s);
        __syncthreads();
        if (lane == 0) sm.red[wid] = fv;
        __syncthreads();
        if (tid == 0) {
            float a = 0.f;
#pragma unroll
            for (int w = 0; w < 8; w++) a += sm.red[w];
            g_fea1[bx] = a;
        }
    }

    // last-block finalize (deterministic fixed-order sums)
    if (tid == 0) {
        __threadfence();
        int prev = atomicAdd(&g_done, 1);
        sm.last = (prev == NBLOCKS - 1) ? 1 : 0;
    }
    __syncthreads();
    if (sm.last && wid == 0) {
        float S = 0.f;
        for (int i = lane; i < NBLOCKS; i += 32) S += g_part[i];
        float Ff = 0.f;
        for (int i = lane; i < MBLK; i += 32) Ff += g_fea1[i];
        for (int i = lane; i < NCHUNKS; i += 32) Ff += g_fea2[i];
#pragma unroll
        for (int s = 16; s > 0; s >>= 1) {
            S  += __shfl_down_sync(0xFFFFFFFF, S, s);
            Ff += __shfl_down_sync(0xFFFFFFFF, Ff, s);
        }
        if (lane == 0) {
            float inner = -S * (1.0f / (float)N_PIX);
            if (out_size > 0) out[0] = inner;        // final_loss
            if (out_size > 1) out[1] = inner;        // inner_neg
            if (out_size > 2) out[2] = Ff * 100.0f;  // fea_norm_sum
            g_done = 0;                              // reset for next replay
        }
        for (int i = 3 + lane; i < out_size; i += 32) out[i] = 0.0f;
    }
}

extern "C" void kernel_launch(void* const* d_in, const int* in_sizes, int n_in,
                              void* d_out, int out_size)
{
    const float* f1    = (const float*)d_in[0];
    const float* f2    = (const float*)d_in[1];
    const float* dp1   = (const float*)d_in[2];
    const float* dp2   = (const float*)d_in[3];
    const float* pose  = (const float*)d_in[4];
    const float* noise = (const float*)d_in[5];

    precompute_kernel<<<NCHUNKS, 64>>>(f2, dp2, pose, noise);
    dim3 grid(MBLK, NSPLIT);
    main_kernel<<<grid, THREADS>>>(f1, dp1, (float*)d_out, out_size);
}

// round 17
// speedup vs baseline: 1.7944x; 1.7944x over previous
#include <cuda_runtime.h>
#include <cuda_fp16.h>
#include <cstdint>

#define N_PIX   6912
#define WIDTH   96
#define CFEAT   16
#define CHUNK   64
#define NCHUNKS 108                 // N_PIX / CHUNK
#define MBLK    108                 // m-blocks of 64 rows (4 warps x 16 rows)
#define NSPLIT  12                  // column splits
#define CPC     (NCHUNKS / NSPLIT)  // 9 chunks per CTA
#define NBLOCKS (MBLK * NSPLIT)     // 1296 (~single wave at ~8 CTA/SM)
#define THREADS 128
#define NWARP   4
#define LOG2E   1.4426950408889634f
// geometry: 80B block per 2 columns (64B data + 16B pad) -> conflict-free lane groups
#define GBLK    80
#define GCHUNK  (32 * GBLK)         // 2560 B per chunk
#define GCP16   (GCHUNK / 16)       // 160 packets
// f2n: row stride 144B (36 words == 4 mod 32 -> conflict-free rows)
#define FSTRIDE 144
#define FCHUNK  (16 * FSTRIDE)      // 2304 B
#define FCP16   (FCHUNK / 16)       // 144 packets

typedef unsigned long long u64;

__device__ __forceinline__ u64 pk2(float lo, float hi) {
    u64 r; asm("mov.b64 %0, {%1, %2};" : "=l"(r) : "f"(lo), "f"(hi)); return r;
}
__device__ __forceinline__ void unpk2(float& lo, float& hi, u64 v) {
    asm("mov.b64 {%0, %1}, %2;" : "=f"(lo), "=f"(hi) : "l"(v));
}
__device__ __forceinline__ u64 fma2(u64 a, u64 b, u64 c) {
    u64 r; asm("fma.rn.f32x2 %0, %1, %2, %3;" : "=l"(r) : "l"(a), "l"(b), "l"(c)); return r;
}
__device__ __forceinline__ u64 add2(u64 a, u64 b) {
    u64 r; asm("add.rn.f32x2 %0, %1, %2;" : "=l"(r) : "l"(a), "l"(b)); return r;
}
__device__ __forceinline__ float ex2f(float a) {
    float r; asm("ex2.approx.ftz.f32 %0, %1;" : "=f"(r) : "f"(a)); return r;
}
__device__ __forceinline__ uint32_t pkh2(float hi, float lo) {
    uint32_t r; asm("cvt.rn.f16x2.f32 %0, %1, %2;" : "=r"(r) : "f"(hi), "f"(lo)); return r;
}
__device__ __forceinline__ uint32_t sm_u32(const void* p) {
    uint32_t a;
    asm("{ .reg .u64 t; cvta.to.shared.u64 t, %1; cvt.u32.u64 %0, t; }" : "=r"(a) : "l"(p));
    return a;
}
__device__ __forceinline__ void cpasync16(uint32_t sa, const void* g) {
    asm volatile("cp.async.ca.shared.global [%0], [%1], 16;" :: "r"(sa), "l"(g) : "memory");
}
// m16n8k16 row.col f16 inputs, f32 accumulate (sm_80+, legal at compute_103)
__device__ __forceinline__ void mma16816(float* c, uint32_t a0, uint32_t a1,
                                         uint32_t a2, uint32_t a3,
                                         uint32_t b0, uint32_t b1) {
    asm volatile(
        "mma.sync.aligned.m16n8k16.row.col.f32.f16.f16.f32 "
        "{%0,%1,%2,%3}, {%4,%5,%6,%7}, {%8,%9}, {%0,%1,%2,%3};"
        : "+f"(c[0]), "+f"(c[1]), "+f"(c[2]), "+f"(c[3])
        : "r"(a0), "r"(a1), "r"(a2), "r"(a3), "r"(b0), "r"(b1));
}
// b = x.p - h1 - h2 (exp2 domain, packed clean/noisy); returns e1 - e2 in f32
__device__ __forceinline__ float dexp(ulonglong2 g0, ulonglong2 g1,
                                      u64 X, u64 Y, u64 Z, u64 H) {
    u64 aa = fma2(X, g0.x, H);
    aa = fma2(Y, g0.y, aa);
    aa = fma2(Z, g1.x, aa);
    aa = add2(aa, g1.y);
    float p1, p2; unpk2(p1, p2, aa);
    return ex2f(p1) - ex2f(p2);
}

// Scratch globals (no allocation allowed)
__device__ unsigned char g_geo[NCHUNKS * GCHUNK];    // per chunk: 32 x 80B two-column blocks
__device__ unsigned char g_f2n[NCHUNKS * FCHUNK];    // per chunk: [16 chan][64 col] f16, stride 144B
__device__ float g_part[NBLOCKS];
__device__ float g_fea1[MBLK];
__device__ float g_fea2[NCHUNKS];
__device__ int   g_done = 0;

__global__ __launch_bounds__(64) void precompute_kernel(
    const float* __restrict__ f2, const float* __restrict__ dp2,
    const float* __restrict__ pose, const float* __restrict__ noise)
{
    int tid = threadIdx.x;
    int i = blockIdx.x * 64 + tid;        // block == chunk, tid == column

    float PN[12];
#pragma unroll
    for (int r = 0; r < 3; r++)
#pragma unroll
        for (int c = 0; c < 4; c++) {
            float s = 0.0f;
#pragma unroll
            for (int k = 0; k < 4; k++) s = fmaf(pose[r * 4 + k], noise[k * 4 + c], s);
            PN[r * 4 + c] = s;
        }

    int u = i % WIDTH, v = i / WIDTH;
    float y1 = ((float)u - 48.0f) * (1.0f / 48.0f);
    float y2 = ((float)v - 36.0f) * (1.0f / 48.0f);

    float d2 = dp2[i];
    float q0 = d2, q1 = y1 * d2, q2 = y2 * d2;
    float P[3], Pn[3];
#pragma unroll
    for (int r = 0; r < 3; r++) {
        P[r]  = fmaf(pose[r * 4 + 0], q0, fmaf(pose[r * 4 + 1], q1,
                fmaf(pose[r * 4 + 2], q2, pose[r * 4 + 3])));
        Pn[r] = fmaf(PN[r * 4 + 0], q0, fmaf(PN[r * 4 + 1], q1,
                fmaf(PN[r * 4 + 2], q2, PN[r * 4 + 3])));
    }
    float mh2  = -0.5f * LOG2E * (P[0] * P[0] + P[1] * P[1] + P[2] * P[2]);
    float mh2n = -0.5f * LOG2E * (Pn[0] * Pn[0] + Pn[1] * Pn[1] + Pn[2] * Pn[2]);

    // 80B-block geometry layout: col c -> block c>>1, slot (c&1)*32
    unsigned char* gp = g_geo + (size_t)blockIdx.x * GCHUNK + (tid >> 1) * GBLK + (tid & 1) * 32;
    ulonglong2 ga, gb;
    ga.x = pk2(P[0], Pn[0]); ga.y = pk2(P[1], Pn[1]);
    gb.x = pk2(P[2], Pn[2]); gb.y = pk2(mh2, mh2n);
    *(ulonglong2*)(gp + 0)  = ga;
    *(ulonglong2*)(gp + 16) = gb;

    float b[CFEAT], s2 = 0.0f;
#pragma unroll
    for (int c = 0; c < CFEAT; c++) { b[c] = f2[c * N_PIX + i]; s2 = fmaf(b[c], b[c], s2); }
    float n2 = sqrtf(s2);
    float sc = 1.0f / (n2 + 1e-8f);

    unsigned char* dst = g_f2n + (size_t)blockIdx.x * FCHUNK;
#pragma unroll
    for (int c = 0; c < CFEAT; c++)
        *(__half*)(dst + c * FSTRIDE + tid * 2) = __float2half_rn(b[c] * sc);

    __shared__ float red[2];
    float r = n2;
#pragma unroll
    for (int s = 16; s > 0; s >>= 1) r += __shfl_down_sync(0xFFFFFFFF, r, s);
    if ((tid & 31) == 0) red[tid >> 5] = r;
    __syncthreads();
    if (tid == 0) g_fea2[blockIdx.x] = red[0] + red[1];
}

struct Smem {
    alignas(16) unsigned char G[2][GCHUNK];  // geometry chunk (2560B)
    alignas(16) unsigned char F[2][FCHUNK];  // f2n chunk (2304B)
    float red[NWARP];
    int last;
};

__global__ __launch_bounds__(THREADS, 8) void main_kernel(
    const float* __restrict__ f1, const float* __restrict__ dp1,
    float* __restrict__ out, int out_size)
{
    __shared__ Smem sm;

    int tid = threadIdx.x;
    int lane = tid & 31;
    int wid = tid >> 5;
    int bx = blockIdx.x, by = blockIdx.y;

    // rows owned by this thread (mma A-fragment rows)
    int rowbase = bx * 64 + wid * 16;
    int r0 = rowbase + (lane >> 2);
    int r8 = r0 + 8;

    // packed (clean,noisy) geometry per row, exp2 domain
    u64 X0, Y0, Z0, H0, X8, Y8, Z8, H8;
    {
        int rr[2] = { r0, r8 };
        u64* dst[2][4] = { {&X0, &Y0, &Z0, &H0}, {&X8, &Y8, &Z8, &H8} };
#pragma unroll
        for (int t = 0; t < 2; t++) {
            int m = rr[t];
            int uu = m % WIDTH, vv = m / WIDTH;
            float y1 = ((float)uu - 48.0f) * (1.0f / 48.0f);
            float y2 = ((float)vv - 36.0f) * (1.0f / 48.0f);
            float d = dp1[m];
            float xx = d, xy = y1 * d, xz = y2 * d;
            float h1L = 0.5f * LOG2E * (xx * xx + xy * xy + xz * xz);
            *dst[t][0] = pk2(xx * LOG2E, xx * LOG2E);
            *dst[t][1] = pk2(xy * LOG2E, xy * LOG2E);
            *dst[t][2] = pk2(xz * LOG2E, xz * LOG2E);
            *dst[t][3] = pk2(-h1L, -h1L);
        }
    }

    float accA[4] = {0.f, 0.f, 0.f, 0.f};   // channels 0-7
    float accB[4] = {0.f, 0.f, 0.f, 0.f};   // channels 8-15

    int c0c = by * CPC;
    // prologue: prefetch chunk 0 into buffer 0
    {
        const unsigned char* gs = g_geo + (size_t)c0c * GCHUNK;
        for (int i = tid; i < GCP16; i += THREADS) cpasync16(sm_u32(sm.G[0] + i * 16), gs + i * 16);
        const unsigned char* fs = g_f2n + (size_t)c0c * FCHUNK;
        for (int i = tid; i < FCP16; i += THREADS) cpasync16(sm_u32(sm.F[0] + i * 16), fs + i * 16);
        asm volatile("cp.async.commit_group;" ::: "memory");
    }

    for (int ci = 0; ci < CPC; ci++) {
        asm volatile("cp.async.wait_group 0;" ::: "memory");
        __syncthreads();   // chunk ci staged AND all warps done with the buffer being refilled next

        if (ci + 1 < CPC) {
            int ch = c0c + ci + 1, nb = (ci + 1) & 1;
            const unsigned char* gs = g_geo + (size_t)ch * GCHUNK;
            for (int i = tid; i < GCP16; i += THREADS) cpasync16(sm_u32(sm.G[nb] + i * 16), gs + i * 16);
            const unsigned char* fs = g_f2n + (size_t)ch * FCHUNK;
            for (int i = tid; i < FCP16; i += THREADS) cpasync16(sm_u32(sm.F[nb] + i * 16), fs + i * 16);
            asm volatile("cp.async.commit_group;" ::: "memory");
        }

        int cur = ci & 1;
        const unsigned char* Gb = sm.G[cur];
        const unsigned char* Fb = sm.F[cur];

        // B fragments for this chunk: b[kstep][chanhalf][2]  (conflict-free, stride 144)
        uint32_t bfr[4][2][2];
#pragma unroll
        for (int ks = 0; ks < 4; ks++)
#pragma unroll
            for (int h = 0; h < 2; h++) {
                const unsigned char* p = Fb + ((lane >> 2) + h * 8) * FSTRIDE
                                       + (ks * 16 + (lane & 3) * 2) * 2;
                bfr[ks][h][0] = *(const uint32_t*)p;
                bfr[ks][h][1] = *(const uint32_t*)(p + 16);
            }

#pragma unroll
        for (int ks = 0; ks < 4; ks++) {
            // two-column blocks: q0 covers cols (cb, cb+1), q1 covers (cb+8, cb+9)
            const ulonglong2* q0 = (const ulonglong2*)(Gb + (ks * 8 + (lane & 3)) * GBLK);
            const ulonglong2* q1 = (const ulonglong2*)(Gb + (ks * 8 + (lane & 3) + 4) * GBLK);
            ulonglong2 gA0 = q0[0], gA1 = q0[1];   // col cb
            ulonglong2 gB0 = q0[2], gB1 = q0[3];   // col cb+1
            ulonglong2 gC0 = q1[0], gC1 = q1[1];   // col cb+8
            ulonglong2 gD0 = q1[2], gD1 = q1[3];   // col cb+9

            float dA0 = dexp(gA0, gA1, X0, Y0, Z0, H0);
            float dA8 = dexp(gA0, gA1, X8, Y8, Z8, H8);
            float dB0 = dexp(gB0, gB1, X0, Y0, Z0, H0);
            float dB8 = dexp(gB0, gB1, X8, Y8, Z8, H8);
            float dC0 = dexp(gC0, gC1, X0, Y0, Z0, H0);
            float dC8 = dexp(gC0, gC1, X8, Y8, Z8, H8);
            float dD0 = dexp(gD0, gD1, X0, Y0, Z0, H0);
            float dD8 = dexp(gD0, gD1, X8, Y8, Z8, H8);

            uint32_t a0 = pkh2(dB0, dA0);   // row r0, cols (cb, cb+1)
            uint32_t a1 = pkh2(dB8, dA8);   // row r8
            uint32_t a2 = pkh2(dD0, dC0);   // row r0, cols (cb+8, cb+9)
            uint32_t a3 = pkh2(dD8, dC8);   // row r8

            mma16816(accA, a0, a1, a2, a3, bfr[ks][0][0], bfr[ks][0][1]);
            mma16816(accB, a0, a1, a2, a3, bfr[ks][1][0], bfr[ks][1][1]);
        }
        // no trailing sync: next refill of this buffer happens after next top-of-loop sync
    }

    // epilogue: dot accumulators with normalized f1 rows
    int ch0 = (lane & 3) * 2, ch1 = ch0 + 1;
    float s0 = 0.f, s8 = 0.f;
#pragma unroll
    for (int c = 0; c < CFEAT; c++) {
        float v0 = f1[c * N_PIX + r0]; s0 = fmaf(v0, v0, s0);
        float v8 = f1[c * N_PIX + r8]; s8 = fmaf(v8, v8, s8);
    }
    float n10 = sqrtf(s0), n18 = sqrtf(s8);
    float inv0 = 1.0f / (n10 + 1e-8f), inv8 = 1.0f / (n18 + 1e-8f);

    float d0 = f1[ch0 * N_PIX + r0] * accA[0] + f1[ch1 * N_PIX + r0] * accA[1]
             + f1[(ch0 + 8) * N_PIX + r0] * accB[0] + f1[(ch1 + 8) * N_PIX + r0] * accB[1];
    float d8 = f1[ch0 * N_PIX + r8] * accA[2] + f1[ch1 * N_PIX + r8] * accA[3]
             + f1[(ch0 + 8) * N_PIX + r8] * accB[2] + f1[(ch1 + 8) * N_PIX + r8] * accB[3];
    float dot = inv0 * d0 + inv8 * d8;

    __syncthreads();   // compute done before reusing sm.red
#pragma unroll
    for (int s = 16; s > 0; s >>= 1) dot += __shfl_down_sync(0xFFFFFFFF, dot, s);
    if (lane == 0) sm.red[wid] = dot;
    __syncthreads();
    if (tid == 0) {
        float a = 0.f;
#pragma unroll
        for (int w = 0; w < NWARP; w++) a += sm.red[w];
        g_part[bx * NSPLIT + by] = a;
    }

    if (by == 0) {
        float fv = ((lane & 3) == 0) ? (n10 + n18) : 0.f;   // each row counted once
#pragma unroll
        for (int s = 16; s > 0; s >>= 1) fv += __shfl_down_sync(0xFFFFFFFF, fv, s);
        __syncthreads();
        if (lane == 0) sm.red[wid] = fv;
        __syncthreads();
        if (tid == 0) {
            float a = 0.f;
#pragma unroll
            for (int w = 0; w < NWARP; w++) a += sm.red[w];
            g_fea1[bx] = a;
        }
    }

    // last-block finalize (deterministic fixed-order sums)
    if (tid == 0) {
        __threadfence();
        int prev = atomicAdd(&g_done, 1);
        sm.last = (prev == NBLOCKS - 1) ? 1 : 0;
    }
    __syncthreads();
    if (sm.last && wid == 0) {
        float S = 0.f;
        for (int i = lane; i < NBLOCKS; i += 32) S += g_part[i];
        float Ff = 0.f;
        for (int i = lane; i < MBLK; i += 32) Ff += g_fea1[i];
        for (int i = lane; i < NCHUNKS; i += 32) Ff += g_fea2[i];
#pragma unroll
        for (int s = 16; s > 0; s >>= 1) {
            S  += __shfl_down_sync(0xFFFFFFFF, S, s);
            Ff += __shfl_down_sync(0xFFFFFFFF, Ff, s);
        }
        if (lane == 0) {
            float inner = -S * (1.0f / (float)N_PIX);
            if (out_size > 0) out[0] = inner;        // final_loss
            if (out_size > 1) out[1] = inner;        // inner_neg
            if (out_size > 2) out[2] = Ff * 100.0f;  // fea_norm_sum
            g_done = 0;                              // reset for next replay
        }
        for (int i = 3 + lane; i < out_size; i += 32) out[i] = 0.0f;
    }
}

extern "C" void kernel_launch(void* const* d_in, const int* in_sizes, int n_in,
                              void* d_out, int out_size)
{
    const float* f1    = (const float*)d_in[0];
    const float* f2    = (const float*)d_in[1];
    const float* dp1   = (const float*)d_in[2];
    const float* dp2   = (const float*)d_in[3];
    const float* pose  = (const float*)d_in[4];
    const float* noise = (const float*)d_in[5];

    precompute_kernel<<<NCHUNKS, 64>>>(f2, dp2, pose, noise);
    dim3 grid(MBLK, NSPLIT);
    main_kernel<<<grid, THREADS>>>(f1, dp1, (float*)d_out, out_size);
}